// round 2
// baseline (speedup 1.0000x reference)
#include <cuda_runtime.h>
#include <cuda_bf16.h>
#include <math.h>

// Problem constants (fixed by the reference)
#define N_NODES_MAX 50000
#define FEAT 128
#define OUTF 384            // 3 * FEAT
#define N_RBF 20

// Scratch for phi_nodes = (silu(s@W1+b1))@W2 + b2   [N_NODES, 384]
__device__ float g_phi[N_NODES_MAX * OUTF];

// ---------------------------------------------------------------------------
// Kernel A: fused node MLP.  Each block computes a 64-row tile of phi_nodes.
//   smem: sa[64][136] (s tile, then reused for h tile), sw[128][128] (W chunk)
// ---------------------------------------------------------------------------
constexpr int BM  = 64;
constexpr int LDA = 136;                       // padded row stride (bank-safe, 16B aligned)
constexpr int NODE_SMEM_BYTES = (BM * LDA + 128 * 128) * (int)sizeof(float);

__global__ __launch_bounds__(256, 2)
void node_mlp_kernel(const float* __restrict__ s,
                     const float* __restrict__ W1, const float* __restrict__ b1,
                     const float* __restrict__ W2, const float* __restrict__ b2,
                     int n_nodes)
{
    extern __shared__ float sm[];
    float* sa = sm;                 // [BM][LDA]
    float* sw = sm + BM * LDA;      // [128][128]

    const int tid = threadIdx.x;
    const int tx = tid & 15;        // 0..15  -> column groups
    const int ty = tid >> 4;        // 0..15  -> row groups (4 rows each)
    const int row0 = blockIdx.x * BM;

    // ---- stage s tile (64 x 128) ----
    for (int i = tid; i < BM * 32; i += 256) {
        int r = i >> 5, c4 = (i & 31) << 2;
        float4 v = make_float4(0.f, 0.f, 0.f, 0.f);
        if (row0 + r < n_nodes)
            v = *(const float4*)&s[(size_t)(row0 + r) * FEAT + c4];
        *(float4*)&sa[r * LDA + c4] = v;
    }
    // ---- stage W1 (128 x 128) ----
    for (int i = tid; i < 128 * 32; i += 256) {
        int r = i >> 5, c4 = (i & 31) << 2;
        *(float4*)&sw[r * 128 + c4] = *(const float4*)&W1[r * FEAT + c4];
    }
    __syncthreads();

    // ---- GEMM1: h = s @ W1 ----
    float acc[4][8];
#pragma unroll
    for (int i = 0; i < 4; i++)
#pragma unroll
        for (int j = 0; j < 8; j++) acc[i][j] = 0.f;

#pragma unroll 4
    for (int k = 0; k < 128; k++) {
        float4 w0 = *(const float4*)&sw[k * 128 + tx * 4];
        float4 w1 = *(const float4*)&sw[k * 128 + tx * 4 + 64];
        float a[4];
#pragma unroll
        for (int i = 0; i < 4; i++) a[i] = sa[(ty * 4 + i) * LDA + k];
#pragma unroll
        for (int i = 0; i < 4; i++) {
            acc[i][0] = fmaf(a[i], w0.x, acc[i][0]);
            acc[i][1] = fmaf(a[i], w0.y, acc[i][1]);
            acc[i][2] = fmaf(a[i], w0.z, acc[i][2]);
            acc[i][3] = fmaf(a[i], w0.w, acc[i][3]);
            acc[i][4] = fmaf(a[i], w1.x, acc[i][4]);
            acc[i][5] = fmaf(a[i], w1.y, acc[i][5]);
            acc[i][6] = fmaf(a[i], w1.z, acc[i][6]);
            acc[i][7] = fmaf(a[i], w1.w, acc[i][7]);
        }
    }

    // ---- bias + SiLU ----
    float4 b1v0 = *(const float4*)&b1[tx * 4];
    float4 b1v1 = *(const float4*)&b1[tx * 4 + 64];
    float h[4][8];
#pragma unroll
    for (int i = 0; i < 4; i++) {
        float bb[8] = {b1v0.x, b1v0.y, b1v0.z, b1v0.w, b1v1.x, b1v1.y, b1v1.z, b1v1.w};
#pragma unroll
        for (int j = 0; j < 8; j++) {
            float x = acc[i][j] + bb[j];
            h[i][j] = x / (1.0f + expf(-x));
        }
    }
    __syncthreads();   // all reads of sa done -> safe to overwrite with h

    // ---- store h into sa (same layout) ----
#pragma unroll
    for (int i = 0; i < 4; i++) {
        float4 v0 = make_float4(h[i][0], h[i][1], h[i][2], h[i][3]);
        float4 v1 = make_float4(h[i][4], h[i][5], h[i][6], h[i][7]);
        *(float4*)&sa[(ty * 4 + i) * LDA + tx * 4]      = v0;
        *(float4*)&sa[(ty * 4 + i) * LDA + tx * 4 + 64] = v1;
    }

    // ---- GEMM2: phi = h @ W2 (+b2), 3 column chunks of 128 ----
    for (int ch = 0; ch < 3; ch++) {
        __syncthreads();  // h visible; previous sw readers done
        for (int i = tid; i < 128 * 32; i += 256) {
            int r = i >> 5, c4 = (i & 31) << 2;
            *(float4*)&sw[r * 128 + c4] =
                *(const float4*)&W2[(size_t)r * OUTF + ch * 128 + c4];
        }
        __syncthreads();

        float acc2[4][8];
#pragma unroll
        for (int i = 0; i < 4; i++)
#pragma unroll
            for (int j = 0; j < 8; j++) acc2[i][j] = 0.f;

#pragma unroll 4
        for (int k = 0; k < 128; k++) {
            float4 w0 = *(const float4*)&sw[k * 128 + tx * 4];
            float4 w1 = *(const float4*)&sw[k * 128 + tx * 4 + 64];
            float a[4];
#pragma unroll
            for (int i = 0; i < 4; i++) a[i] = sa[(ty * 4 + i) * LDA + k];
#pragma unroll
            for (int i = 0; i < 4; i++) {
                acc2[i][0] = fmaf(a[i], w0.x, acc2[i][0]);
                acc2[i][1] = fmaf(a[i], w0.y, acc2[i][1]);
                acc2[i][2] = fmaf(a[i], w0.z, acc2[i][2]);
                acc2[i][3] = fmaf(a[i], w0.w, acc2[i][3]);
                acc2[i][4] = fmaf(a[i], w1.x, acc2[i][4]);
                acc2[i][5] = fmaf(a[i], w1.y, acc2[i][5]);
                acc2[i][6] = fmaf(a[i], w1.z, acc2[i][6]);
                acc2[i][7] = fmaf(a[i], w1.w, acc2[i][7]);
            }
        }

        float4 b2v0 = *(const float4*)&b2[ch * 128 + tx * 4];
        float4 b2v1 = *(const float4*)&b2[ch * 128 + tx * 4 + 64];
#pragma unroll
        for (int i = 0; i < 4; i++) {
            int r = row0 + ty * 4 + i;
            if (r < n_nodes) {
                float4 o0 = make_float4(acc2[i][0] + b2v0.x, acc2[i][1] + b2v0.y,
                                        acc2[i][2] + b2v0.z, acc2[i][3] + b2v0.w);
                float4 o1 = make_float4(acc2[i][4] + b2v1.x, acc2[i][5] + b2v1.y,
                                        acc2[i][6] + b2v1.z, acc2[i][7] + b2v1.w);
                *(float4*)&g_phi[(size_t)r * OUTF + ch * 128 + tx * 4]      = o0;
                *(float4*)&g_phi[(size_t)r * OUTF + ch * 128 + tx * 4 + 64] = o1;
            }
        }
    }
}

// ---------------------------------------------------------------------------
// Kernel B: fused edge kernel.
//   One block = 8 edges x 384 output columns. Thread k holds Wd[:,k] in regs.
//   RBF: one sincosf per edge + Chebyshev recurrence; premultiplied by env/d.
//   out[e,k] = phi[j_e,k] * (env*bd[k] + sum_n (env*sin(n th)/d) * Wd[n,k])
// ---------------------------------------------------------------------------
constexpr int EPB = 8;

__global__ __launch_bounds__(384)
void edge_kernel(const float* __restrict__ dist,
                 const int* __restrict__ nbrs,          // int32 pairs (i, j)
                 const float* __restrict__ Wd, const float* __restrict__ bd,
                 float* __restrict__ out, int n_edges, int n_nodes)
{
    __shared__ float srbf[EPB][N_RBF];   // env*sin(n th)/d, 80B rows (16B aligned)
    __shared__ float senv[EPB];
    __shared__ int   sj[EPB];

    const int k = threadIdx.x;           // output column 0..383
    float wd[N_RBF];
#pragma unroll
    for (int n = 0; n < N_RBF; n++) wd[n] = __ldg(&Wd[n * OUTF + k]);
    const float bdk = __ldg(&bd[k]);

    const int e0 = blockIdx.x * EPB;

    if (k < EPB) {
        int e = e0 + k;
        float d = (e < n_edges) ? dist[e] : 1.0f;
        float th = d * 0.62831853071795864769f;        // pi/5
        float sn, cs;
        sincosf(th, &sn, &cs);
        float inv = (d == 0.0f) ? 0.0f : (1.0f / d);
        float env = (d < 5.0f) ? (0.5f * (cs + 1.0f)) : 0.0f;
        float scale = env * inv;
        senv[k] = env;
        int j = (e < n_edges) ? nbrs[2 * e + 1] : 0;
        // clamp defensively: a bad index becomes a wrong value (visible in
        // rel_err) instead of an illegal access (no signal at all)
        j = (j < 0) ? 0 : ((j >= n_nodes) ? (n_nodes - 1) : j);
        sj[k] = j;

        float sm1 = sn, sm0 = 0.0f;
        float twoc = 2.0f * cs;
        srbf[k][0] = sn * scale;
#pragma unroll
        for (int n = 1; n < N_RBF; n++) {
            float snn = fmaf(twoc, sm1, -sm0);
            sm0 = sm1; sm1 = snn;
            srbf[k][n] = snn * scale;
        }
    }
    __syncthreads();

#pragma unroll
    for (int i = 0; i < EPB; i++) {
        int e = e0 + i;
        if (e >= n_edges) return;
        float4 r0 = *(const float4*)&srbf[i][0];
        float4 r1 = *(const float4*)&srbf[i][4];
        float4 r2 = *(const float4*)&srbf[i][8];
        float4 r3 = *(const float4*)&srbf[i][12];
        float4 r4 = *(const float4*)&srbf[i][16];

        float acc = senv[i] * bdk;
        acc = fmaf(r0.x, wd[0],  acc);
        acc = fmaf(r0.y, wd[1],  acc);
        acc = fmaf(r0.z, wd[2],  acc);
        acc = fmaf(r0.w, wd[3],  acc);
        acc = fmaf(r1.x, wd[4],  acc);
        acc = fmaf(r1.y, wd[5],  acc);
        acc = fmaf(r1.z, wd[6],  acc);
        acc = fmaf(r1.w, wd[7],  acc);
        acc = fmaf(r2.x, wd[8],  acc);
        acc = fmaf(r2.y, wd[9],  acc);
        acc = fmaf(r2.z, wd[10], acc);
        acc = fmaf(r2.w, wd[11], acc);
        acc = fmaf(r3.x, wd[12], acc);
        acc = fmaf(r3.y, wd[13], acc);
        acc = fmaf(r3.z, wd[14], acc);
        acc = fmaf(r3.w, wd[15], acc);
        acc = fmaf(r4.x, wd[16], acc);
        acc = fmaf(r4.y, wd[17], acc);
        acc = fmaf(r4.z, wd[18], acc);
        acc = fmaf(r4.w, wd[19], acc);

        float ph = __ldg(&g_phi[(size_t)sj[i] * OUTF + k]);
        out[(size_t)e * OUTF + k] = ph * acc;
    }
}

// ---------------------------------------------------------------------------
// Launch
//   inputs: s_j[N*128] f32, dist[E] f32, nbrs[E*2] int32, W1[128*128], b1[128],
//           W2[128*384], b2[384], Wd[20*384], bd[384]
// ---------------------------------------------------------------------------
extern "C" void kernel_launch(void* const* d_in, const int* in_sizes, int n_in,
                              void* d_out, int out_size)
{
    const float* s    = (const float*)d_in[0];
    const float* dist = (const float*)d_in[1];
    const int*   nbrs = (const int*)d_in[2];     // int32 (JAX x64 disabled)
    const float* W1   = (const float*)d_in[3];
    const float* b1   = (const float*)d_in[4];
    const float* W2   = (const float*)d_in[5];
    const float* b2   = (const float*)d_in[6];
    const float* Wd   = (const float*)d_in[7];
    const float* bd   = (const float*)d_in[8];
    float* out = (float*)d_out;

    const int n_nodes = in_sizes[0] / FEAT;
    const int n_edges = in_sizes[1];

    cudaFuncSetAttribute(node_mlp_kernel,
                         cudaFuncAttributeMaxDynamicSharedMemorySize,
                         NODE_SMEM_BYTES);

    int node_blocks = (n_nodes + BM - 1) / BM;
    node_mlp_kernel<<<node_blocks, 256, NODE_SMEM_BYTES>>>(s, W1, b1, W2, b2, n_nodes);

    int edge_blocks = (n_edges + EPB - 1) / EPB;
    edge_kernel<<<edge_blocks, 384>>>(dist, nbrs, Wd, bd, out, n_edges, n_nodes);
}

// round 3
// speedup vs baseline: 1.0152x; 1.0152x over previous
#include <cuda_runtime.h>
#include <cuda_bf16.h>
#include <math.h>

#define N_NODES_MAX 50000
#define FEAT 128
#define OUTF 384
#define N_RBF 20

__device__ float g_phi[N_NODES_MAX * OUTF];

// ---------------------------------------------------------------------------
// Kernel A: fused node MLP (unchanged from R2 — near scalar FMA roofline).
// ---------------------------------------------------------------------------
constexpr int BM  = 64;
constexpr int LDA = 136;
constexpr int NODE_SMEM_BYTES = (BM * LDA + 128 * 128) * (int)sizeof(float);

__global__ __launch_bounds__(256, 2)
void node_mlp_kernel(const float* __restrict__ s,
                     const float* __restrict__ W1, const float* __restrict__ b1,
                     const float* __restrict__ W2, const float* __restrict__ b2,
                     int n_nodes)
{
    extern __shared__ float sm[];
    float* sa = sm;
    float* sw = sm + BM * LDA;

    const int tid = threadIdx.x;
    const int tx = tid & 15;
    const int ty = tid >> 4;
    const int row0 = blockIdx.x * BM;

    for (int i = tid; i < BM * 32; i += 256) {
        int r = i >> 5, c4 = (i & 31) << 2;
        float4 v = make_float4(0.f, 0.f, 0.f, 0.f);
        if (row0 + r < n_nodes)
            v = *(const float4*)&s[(size_t)(row0 + r) * FEAT + c4];
        *(float4*)&sa[r * LDA + c4] = v;
    }
    for (int i = tid; i < 128 * 32; i += 256) {
        int r = i >> 5, c4 = (i & 31) << 2;
        *(float4*)&sw[r * 128 + c4] = *(const float4*)&W1[r * FEAT + c4];
    }
    __syncthreads();

    float acc[4][8];
#pragma unroll
    for (int i = 0; i < 4; i++)
#pragma unroll
        for (int j = 0; j < 8; j++) acc[i][j] = 0.f;

#pragma unroll 4
    for (int k = 0; k < 128; k++) {
        float4 w0 = *(const float4*)&sw[k * 128 + tx * 4];
        float4 w1 = *(const float4*)&sw[k * 128 + tx * 4 + 64];
        float a[4];
#pragma unroll
        for (int i = 0; i < 4; i++) a[i] = sa[(ty * 4 + i) * LDA + k];
#pragma unroll
        for (int i = 0; i < 4; i++) {
            acc[i][0] = fmaf(a[i], w0.x, acc[i][0]);
            acc[i][1] = fmaf(a[i], w0.y, acc[i][1]);
            acc[i][2] = fmaf(a[i], w0.z, acc[i][2]);
            acc[i][3] = fmaf(a[i], w0.w, acc[i][3]);
            acc[i][4] = fmaf(a[i], w1.x, acc[i][4]);
            acc[i][5] = fmaf(a[i], w1.y, acc[i][5]);
            acc[i][6] = fmaf(a[i], w1.z, acc[i][6]);
            acc[i][7] = fmaf(a[i], w1.w, acc[i][7]);
        }
    }

    float4 b1v0 = *(const float4*)&b1[tx * 4];
    float4 b1v1 = *(const float4*)&b1[tx * 4 + 64];
    float h[4][8];
#pragma unroll
    for (int i = 0; i < 4; i++) {
        float bb[8] = {b1v0.x, b1v0.y, b1v0.z, b1v0.w, b1v1.x, b1v1.y, b1v1.z, b1v1.w};
#pragma unroll
        for (int j = 0; j < 8; j++) {
            float x = acc[i][j] + bb[j];
            h[i][j] = x / (1.0f + expf(-x));
        }
    }
    __syncthreads();

#pragma unroll
    for (int i = 0; i < 4; i++) {
        float4 v0 = make_float4(h[i][0], h[i][1], h[i][2], h[i][3]);
        float4 v1 = make_float4(h[i][4], h[i][5], h[i][6], h[i][7]);
        *(float4*)&sa[(ty * 4 + i) * LDA + tx * 4]      = v0;
        *(float4*)&sa[(ty * 4 + i) * LDA + tx * 4 + 64] = v1;
    }

    for (int ch = 0; ch < 3; ch++) {
        __syncthreads();
        for (int i = tid; i < 128 * 32; i += 256) {
            int r = i >> 5, c4 = (i & 31) << 2;
            *(float4*)&sw[r * 128 + c4] =
                *(const float4*)&W2[(size_t)r * OUTF + ch * 128 + c4];
        }
        __syncthreads();

        float acc2[4][8];
#pragma unroll
        for (int i = 0; i < 4; i++)
#pragma unroll
            for (int j = 0; j < 8; j++) acc2[i][j] = 0.f;

#pragma unroll 4
        for (int k = 0; k < 128; k++) {
            float4 w0 = *(const float4*)&sw[k * 128 + tx * 4];
            float4 w1 = *(const float4*)&sw[k * 128 + tx * 4 + 64];
            float a[4];
#pragma unroll
            for (int i = 0; i < 4; i++) a[i] = sa[(ty * 4 + i) * LDA + k];
#pragma unroll
            for (int i = 0; i < 4; i++) {
                acc2[i][0] = fmaf(a[i], w0.x, acc2[i][0]);
                acc2[i][1] = fmaf(a[i], w0.y, acc2[i][1]);
                acc2[i][2] = fmaf(a[i], w0.z, acc2[i][2]);
                acc2[i][3] = fmaf(a[i], w0.w, acc2[i][3]);
                acc2[i][4] = fmaf(a[i], w1.x, acc2[i][4]);
                acc2[i][5] = fmaf(a[i], w1.y, acc2[i][5]);
                acc2[i][6] = fmaf(a[i], w1.z, acc2[i][6]);
                acc2[i][7] = fmaf(a[i], w1.w, acc2[i][7]);
            }
        }

        float4 b2v0 = *(const float4*)&b2[ch * 128 + tx * 4];
        float4 b2v1 = *(const float4*)&b2[ch * 128 + tx * 4 + 64];
#pragma unroll
        for (int i = 0; i < 4; i++) {
            int r = row0 + ty * 4 + i;
            if (r < n_nodes) {
                float4 o0 = make_float4(acc2[i][0] + b2v0.x, acc2[i][1] + b2v0.y,
                                        acc2[i][2] + b2v0.z, acc2[i][3] + b2v0.w);
                float4 o1 = make_float4(acc2[i][4] + b2v1.x, acc2[i][5] + b2v1.y,
                                        acc2[i][6] + b2v1.z, acc2[i][7] + b2v1.w);
                *(float4*)&g_phi[(size_t)r * OUTF + ch * 128 + tx * 4]      = o0;
                *(float4*)&g_phi[(size_t)r * OUTF + ch * 128 + tx * 4 + 64] = o1;
            }
        }
    }
}

// ---------------------------------------------------------------------------
// Kernel B (restructured): float4 per thread, prefetched gathers.
//   384 threads = 4 edge-groups x 96 column-groups (4 cols each).
//   Thread holds Wd[:, c0..c0+3] in 80 registers. 16 edges/block,
//   4 edges per group; all 4 gather LDG.128 issued before compute.
// ---------------------------------------------------------------------------
constexpr int EPB = 16;   // edges per block
constexpr int NG  = 4;    // edge groups per block
constexpr int EPG = EPB / NG;  // edges per group (per thread)

__global__ __launch_bounds__(384, 1)
void edge_kernel(const float* __restrict__ dist,
                 const int* __restrict__ nbrs,
                 const float* __restrict__ Wd, const float* __restrict__ bd,
                 float* __restrict__ out, int n_edges, int n_nodes)
{
    __shared__ float srbf[EPB][N_RBF];   // env*sin(n th)/d
    __shared__ float senv[EPB];
    __shared__ int   sj[EPB];

    const int tid = threadIdx.x;
    const int g   = tid / 96;            // edge group 0..3
    const int cg  = tid % 96;            // column group
    const int c0  = cg * 4;

    // Wd column block -> registers (80 regs)
    float4 wd[N_RBF];
#pragma unroll
    for (int n = 0; n < N_RBF; n++)
        wd[n] = __ldg((const float4*)&Wd[n * OUTF + c0]);
    const float4 bd4 = __ldg((const float4*)&bd[c0]);

    const int e0 = blockIdx.x * EPB;

    if (tid < EPB) {
        int e = e0 + tid;
        float d = (e < n_edges) ? dist[e] : 1.0f;
        float th = d * 0.62831853071795864769f;   // pi/5
        float sn, cs;
        sincosf(th, &sn, &cs);
        float inv = (d == 0.0f) ? 0.0f : (1.0f / d);
        float env = (d < 5.0f) ? (0.5f * (cs + 1.0f)) : 0.0f;
        float scale = env * inv;
        senv[tid] = env;
        int j = (e < n_edges) ? nbrs[2 * e + 1] : 0;
        j = (j < 0) ? 0 : ((j >= n_nodes) ? (n_nodes - 1) : j);
        sj[tid] = j;

        float sm1 = sn, sm0 = 0.0f;
        float twoc = 2.0f * cs;
        srbf[tid][0] = sn * scale;
#pragma unroll
        for (int n = 1; n < N_RBF; n++) {
            float snn = fmaf(twoc, sm1, -sm0);
            sm0 = sm1; sm1 = snn;
            srbf[tid][n] = snn * scale;
        }
    }
    __syncthreads();

    // ---- prefetch all gathers for this group's edges (MLP=4) ----
    float4 ph[EPG];
#pragma unroll
    for (int i = 0; i < EPG; i++) {
        int le = g + i * NG;
        int idx = sj[le];                     // safe (0) for OOB edges
        ph[i] = __ldg((const float4*)&g_phi[(size_t)idx * OUTF + c0]);
    }

    // ---- compute + store ----
#pragma unroll
    for (int i = 0; i < EPG; i++) {
        int le = g + i * NG;
        int e  = e0 + le;
        if (e >= n_edges) continue;

        float4 r0 = *(const float4*)&srbf[le][0];
        float4 r1 = *(const float4*)&srbf[le][4];
        float4 r2 = *(const float4*)&srbf[le][8];
        float4 r3 = *(const float4*)&srbf[le][12];
        float4 r4 = *(const float4*)&srbf[le][16];
        float rr[N_RBF] = {r0.x, r0.y, r0.z, r0.w, r1.x, r1.y, r1.z, r1.w,
                           r2.x, r2.y, r2.z, r2.w, r3.x, r3.y, r3.z, r3.w,
                           r4.x, r4.y, r4.z, r4.w};

        float env = senv[le];
        float4 acc = make_float4(env * bd4.x, env * bd4.y,
                                 env * bd4.z, env * bd4.w);
#pragma unroll
        for (int n = 0; n < N_RBF; n++) {
            acc.x = fmaf(rr[n], wd[n].x, acc.x);
            acc.y = fmaf(rr[n], wd[n].y, acc.y);
            acc.z = fmaf(rr[n], wd[n].z, acc.z);
            acc.w = fmaf(rr[n], wd[n].w, acc.w);
        }

        float4 o = make_float4(ph[i].x * acc.x, ph[i].y * acc.y,
                               ph[i].z * acc.z, ph[i].w * acc.w);
        *(float4*)&out[(size_t)e * OUTF + c0] = o;
    }
}

// ---------------------------------------------------------------------------
extern "C" void kernel_launch(void* const* d_in, const int* in_sizes, int n_in,
                              void* d_out, int out_size)
{
    const float* s    = (const float*)d_in[0];
    const float* dist = (const float*)d_in[1];
    const int*   nbrs = (const int*)d_in[2];     // int32
    const float* W1   = (const float*)d_in[3];
    const float* b1   = (const float*)d_in[4];
    const float* W2   = (const float*)d_in[5];
    const float* b2   = (const float*)d_in[6];
    const float* Wd   = (const float*)d_in[7];
    const float* bd   = (const float*)d_in[8];
    float* out = (float*)d_out;

    const int n_nodes = in_sizes[0] / FEAT;
    const int n_edges = in_sizes[1];

    cudaFuncSetAttribute(node_mlp_kernel,
                         cudaFuncAttributeMaxDynamicSharedMemorySize,
                         NODE_SMEM_BYTES);

    int node_blocks = (n_nodes + BM - 1) / BM;
    node_mlp_kernel<<<node_blocks, 256, NODE_SMEM_BYTES>>>(s, W1, b1, W2, b2, n_nodes);

    int edge_blocks = (n_edges + EPB - 1) / EPB;
    edge_kernel<<<edge_blocks, 384>>>(dist, nbrs, Wd, bd, out, n_edges, n_nodes);
}

// round 4
// speedup vs baseline: 1.5941x; 1.5701x over previous
#include <cuda_runtime.h>
#include <cuda_bf16.h>
#include <math.h>

#define N_NODES_MAX 50000
#define FEAT 128
#define OUTF 384
#define N_RBF 20

__device__ float g_phi[N_NODES_MAX * OUTF];

// ---------------- f32x2 packed-math helpers (sm_103a) ----------------
__device__ __forceinline__ unsigned long long pack2(float lo, float hi) {
    unsigned long long r;
    asm("mov.b64 %0, {%1, %2};" : "=l"(r) : "f"(lo), "f"(hi));
    return r;
}
__device__ __forceinline__ unsigned long long dup2(float a) { return pack2(a, a); }
__device__ __forceinline__ void unpack2(unsigned long long v, float& lo, float& hi) {
    asm("mov.b64 {%0, %1}, %2;" : "=f"(lo), "=f"(hi) : "l"(v));
}
__device__ __forceinline__ unsigned long long fma2(unsigned long long a,
                                                   unsigned long long b,
                                                   unsigned long long c) {
    unsigned long long d;
    asm("fma.rn.f32x2 %0, %1, %2, %3;" : "=l"(d) : "l"(a), "l"(b), "l"(c));
    return d;
}
__device__ __forceinline__ unsigned long long mul2(unsigned long long a,
                                                   unsigned long long b) {
    unsigned long long d;
    asm("mul.rn.f32x2 %0, %1, %2;" : "=l"(d) : "l"(a), "l"(b));
    return d;
}

// ---------------------------------------------------------------------------
// Kernel A: fused node MLP with f32x2 packed FFMA.
// ---------------------------------------------------------------------------
constexpr int BM  = 64;
constexpr int LDA = 136;
constexpr int NODE_SMEM_BYTES = (BM * LDA + 128 * 128) * (int)sizeof(float);

__global__ __launch_bounds__(256, 2)
void node_mlp_kernel(const float* __restrict__ s,
                     const float* __restrict__ W1, const float* __restrict__ b1,
                     const float* __restrict__ W2, const float* __restrict__ b2,
                     int n_nodes)
{
    extern __shared__ float sm[];
    float* sa = sm;                 // [BM][LDA]
    float* sw = sm + BM * LDA;      // [128][128]

    const int tid = threadIdx.x;
    const int tx = tid & 15;
    const int ty = tid >> 4;
    const int row0 = blockIdx.x * BM;

    for (int i = tid; i < BM * 32; i += 256) {
        int r = i >> 5, c4 = (i & 31) << 2;
        float4 v = make_float4(0.f, 0.f, 0.f, 0.f);
        if (row0 + r < n_nodes)
            v = *(const float4*)&s[(size_t)(row0 + r) * FEAT + c4];
        *(float4*)&sa[r * LDA + c4] = v;
    }
    for (int i = tid; i < 128 * 32; i += 256) {
        int r = i >> 5, c4 = (i & 31) << 2;
        *(float4*)&sw[r * 128 + c4] = *(const float4*)&W1[r * FEAT + c4];
    }
    __syncthreads();

    // ---- GEMM1: h = s @ W1 (packed col-pairs) ----
    unsigned long long acc[4][4];   // acc[i][j] = cols {base+2j, base+2j+1}
#pragma unroll
    for (int i = 0; i < 4; i++)
#pragma unroll
        for (int j = 0; j < 4; j++) acc[i][j] = 0ull;

#pragma unroll 4
    for (int k = 0; k < 128; k++) {
        ulonglong2 w0 = *(const ulonglong2*)&sw[k * 128 + tx * 4];        // cols tx4..tx4+3
        ulonglong2 w1 = *(const ulonglong2*)&sw[k * 128 + tx * 4 + 64];   // cols +64..+67
#pragma unroll
        for (int i = 0; i < 4; i++) {
            unsigned long long a2 = dup2(sa[(ty * 4 + i) * LDA + k]);
            acc[i][0] = fma2(a2, w0.x, acc[i][0]);
            acc[i][1] = fma2(a2, w0.y, acc[i][1]);
            acc[i][2] = fma2(a2, w1.x, acc[i][2]);
            acc[i][3] = fma2(a2, w1.y, acc[i][3]);
        }
    }

    // ---- bias + SiLU ----
    float4 b1v0 = *(const float4*)&b1[tx * 4];
    float4 b1v1 = *(const float4*)&b1[tx * 4 + 64];
    float bb[8] = {b1v0.x, b1v0.y, b1v0.z, b1v0.w, b1v1.x, b1v1.y, b1v1.z, b1v1.w};
    float h[4][8];
#pragma unroll
    for (int i = 0; i < 4; i++) {
#pragma unroll
        for (int j = 0; j < 4; j++) {
            float lo, hi;
            unpack2(acc[i][j], lo, hi);
            float x0 = lo + bb[2 * j],  x1 = hi + bb[2 * j + 1];
            h[i][2 * j]     = x0 / (1.0f + expf(-x0));
            h[i][2 * j + 1] = x1 / (1.0f + expf(-x1));
        }
    }
    __syncthreads();

#pragma unroll
    for (int i = 0; i < 4; i++) {
        float4 v0 = make_float4(h[i][0], h[i][1], h[i][2], h[i][3]);
        float4 v1 = make_float4(h[i][4], h[i][5], h[i][6], h[i][7]);
        *(float4*)&sa[(ty * 4 + i) * LDA + tx * 4]      = v0;
        *(float4*)&sa[(ty * 4 + i) * LDA + tx * 4 + 64] = v1;
    }

    // ---- GEMM2: phi = h @ W2 (+b2), 3 column chunks of 128 ----
    for (int ch = 0; ch < 3; ch++) {
        __syncthreads();
        for (int i = tid; i < 128 * 32; i += 256) {
            int r = i >> 5, c4 = (i & 31) << 2;
            *(float4*)&sw[r * 128 + c4] =
                *(const float4*)&W2[(size_t)r * OUTF + ch * 128 + c4];
        }
        __syncthreads();

        unsigned long long acc2[4][4];
#pragma unroll
        for (int i = 0; i < 4; i++)
#pragma unroll
            for (int j = 0; j < 4; j++) acc2[i][j] = 0ull;

#pragma unroll 4
        for (int k = 0; k < 128; k++) {
            ulonglong2 w0 = *(const ulonglong2*)&sw[k * 128 + tx * 4];
            ulonglong2 w1 = *(const ulonglong2*)&sw[k * 128 + tx * 4 + 64];
#pragma unroll
            for (int i = 0; i < 4; i++) {
                unsigned long long a2 = dup2(sa[(ty * 4 + i) * LDA + k]);
                acc2[i][0] = fma2(a2, w0.x, acc2[i][0]);
                acc2[i][1] = fma2(a2, w0.y, acc2[i][1]);
                acc2[i][2] = fma2(a2, w1.x, acc2[i][2]);
                acc2[i][3] = fma2(a2, w1.y, acc2[i][3]);
            }
        }

        float4 b2v0 = *(const float4*)&b2[ch * 128 + tx * 4];
        float4 b2v1 = *(const float4*)&b2[ch * 128 + tx * 4 + 64];
        float bc[8] = {b2v0.x, b2v0.y, b2v0.z, b2v0.w, b2v1.x, b2v1.y, b2v1.z, b2v1.w};
#pragma unroll
        for (int i = 0; i < 4; i++) {
            int r = row0 + ty * 4 + i;
            if (r < n_nodes) {
                float o[8];
#pragma unroll
                for (int j = 0; j < 4; j++) {
                    float lo, hi;
                    unpack2(acc2[i][j], lo, hi);
                    o[2 * j] = lo + bc[2 * j];
                    o[2 * j + 1] = hi + bc[2 * j + 1];
                }
                *(float4*)&g_phi[(size_t)r * OUTF + ch * 128 + tx * 4] =
                    make_float4(o[0], o[1], o[2], o[3]);
                *(float4*)&g_phi[(size_t)r * OUTF + ch * 128 + tx * 4 + 64] =
                    make_float4(o[4], o[5], o[6], o[7]);
            }
        }
    }
}

// ---------------------------------------------------------------------------
// Kernel B: two-phase edge kernel.
//   Phase 1: thread k computes w[e][k] = env*(rbf_e . Wd[:,k] + bd[k]) for
//            32 edges, edge-PAIR packed f32x2 FFMA (Wd dup'd into both lanes).
//   Phase 2: pure float4 stream: gather phi, multiply by w (smem), store.
// ---------------------------------------------------------------------------
constexpr int EPB   = 32;            // edges per block
constexpr int WS_LD = 388;           // padded w row (floats), 16B-aligned stride
constexpr int EDGE_SMEM_BYTES =
    (EPB * WS_LD + N_RBF * EPB + EPB + EPB) * (int)sizeof(float);

__global__ __launch_bounds__(384, 2)
void edge_kernel(const float* __restrict__ dist,
                 const int* __restrict__ nbrs,
                 const float* __restrict__ Wd, const float* __restrict__ bd,
                 float* __restrict__ out, int n_edges, int n_nodes)
{
    extern __shared__ float esm[];
    float* w_s    = esm;                         // [EPB][WS_LD]
    float* srbf_t = esm + EPB * WS_LD;           // [N_RBF][EPB] transposed
    float* senv   = srbf_t + N_RBF * EPB;        // [EPB] (8B-aligned offset)
    int*   sj     = (int*)(senv + EPB);          // [EPB]

    const int tid = threadIdx.x;
    const int e0  = blockIdx.x * EPB;

    // ---- setup: one warp computes per-edge scalars + transposed RBF ----
    if (tid < EPB) {
        int e = e0 + tid;
        float d = (e < n_edges) ? dist[e] : 1.0f;
        float th = d * 0.62831853071795864769f;     // pi/5
        float sn, cs;
        sincosf(th, &sn, &cs);
        float inv = (d == 0.0f) ? 0.0f : (1.0f / d);
        float env = (d < 5.0f) ? (0.5f * (cs + 1.0f)) : 0.0f;
        float scale = env * inv;
        senv[tid] = env;
        int j = (e < n_edges) ? nbrs[2 * e + 1] : 0;
        j = (j < 0) ? 0 : ((j >= n_nodes) ? (n_nodes - 1) : j);
        sj[tid] = j;

        float sm1 = sn, sm0 = 0.0f;
        float twoc = 2.0f * cs;
        srbf_t[0 * EPB + tid] = sn * scale;
#pragma unroll
        for (int n = 1; n < N_RBF; n++) {
            float snn = fmaf(twoc, sm1, -sm0);
            sm0 = sm1; sm1 = snn;
            srbf_t[n * EPB + tid] = snn * scale;
        }
    }
    __syncthreads();

    // ---- phase 1: w[e][k] for this thread's column k = tid ----
    {
        const int k = tid;
        unsigned long long wd2[N_RBF];
#pragma unroll
        for (int n = 0; n < N_RBF; n++)
            wd2[n] = dup2(__ldg(&Wd[n * OUTF + k]));
        const unsigned long long bdk2 = dup2(__ldg(&bd[k]));

#pragma unroll
        for (int q = 0; q < EPB / 4; q++) {          // 4 edges per iteration
            unsigned long long envA = *(const unsigned long long*)&senv[4 * q];
            unsigned long long envB = *(const unsigned long long*)&senv[4 * q + 2];
            unsigned long long accA = mul2(envA, bdk2);   // edges 4q, 4q+1
            unsigned long long accB = mul2(envB, bdk2);   // edges 4q+2, 4q+3
#pragma unroll
            for (int n = 0; n < N_RBF; n++) {
                ulonglong2 rr = *(const ulonglong2*)&srbf_t[n * EPB + 4 * q];
                accA = fma2(rr.x, wd2[n], accA);
                accB = fma2(rr.y, wd2[n], accB);
            }
            float a0, a1, a2, a3;
            unpack2(accA, a0, a1);
            unpack2(accB, a2, a3);
            w_s[(4 * q + 0) * WS_LD + k] = a0;
            w_s[(4 * q + 1) * WS_LD + k] = a1;
            w_s[(4 * q + 2) * WS_LD + k] = a2;
            w_s[(4 * q + 3) * WS_LD + k] = a3;
        }
    }
    __syncthreads();

    // ---- phase 2: gather * w -> out, float4 streaming ----
    const int g  = tid / 96;            // edge sub-group 0..3
    const int cg = tid % 96;            // column group (4 cols)
    const int c0 = cg * 4;

    float4 ph[EPB / 4];                 // 8 prefetched gathers
#pragma unroll
    for (int i = 0; i < EPB / 4; i++) {
        int le = g + 4 * i;
        ph[i] = __ldg((const float4*)&g_phi[(size_t)sj[le] * OUTF + c0]);
    }

#pragma unroll
    for (int i = 0; i < EPB / 4; i++) {
        int le = g + 4 * i;
        int e  = e0 + le;
        if (e >= n_edges) continue;
        float4 w4 = *(const float4*)&w_s[le * WS_LD + c0];
        float4 o = make_float4(ph[i].x * w4.x, ph[i].y * w4.y,
                               ph[i].z * w4.z, ph[i].w * w4.w);
        *(float4*)&out[(size_t)e * OUTF + c0] = o;
    }
}

// ---------------------------------------------------------------------------
extern "C" void kernel_launch(void* const* d_in, const int* in_sizes, int n_in,
                              void* d_out, int out_size)
{
    const float* s    = (const float*)d_in[0];
    const float* dist = (const float*)d_in[1];
    const int*   nbrs = (const int*)d_in[2];     // int32
    const float* W1   = (const float*)d_in[3];
    const float* b1   = (const float*)d_in[4];
    const float* W2   = (const float*)d_in[5];
    const float* b2   = (const float*)d_in[6];
    const float* Wd   = (const float*)d_in[7];
    const float* bd   = (const float*)d_in[8];
    float* out = (float*)d_out;

    const int n_nodes = in_sizes[0] / FEAT;
    const int n_edges = in_sizes[1];

    cudaFuncSetAttribute(node_mlp_kernel,
                         cudaFuncAttributeMaxDynamicSharedMemorySize,
                         NODE_SMEM_BYTES);
    cudaFuncSetAttribute(edge_kernel,
                         cudaFuncAttributeMaxDynamicSharedMemorySize,
                         EDGE_SMEM_BYTES);

    int node_blocks = (n_nodes + BM - 1) / BM;
    node_mlp_kernel<<<node_blocks, 256, NODE_SMEM_BYTES>>>(s, W1, b1, W2, b2, n_nodes);

    int edge_blocks = (n_edges + EPB - 1) / EPB;
    edge_kernel<<<edge_blocks, 384, EDGE_SMEM_BYTES>>>(dist, nbrs, Wd, bd, out,
                                                       n_edges, n_nodes);
}